// round 7
// baseline (speedup 1.0000x reference)
#include <cuda_runtime.h>
#include <cstdint>

// Problem constants
#define N_INN   50000
#define NC      64
#define NT      8
#define NE      800000
#define N_OUTN  50000
#define NF      64
#define KD      512   // NT*NC
#define NBLK_SCAN 196 // ceil(50000/256)

// Fused kernel tiling
#define BM      64
#define AS_STRIDE 516                        // 64x516 words, conflict-free
#define AS_WORDS  (BM * AS_STRIDE)           // 33024
#define BS_STRIDE 72
#define BS_WORDS  (32 * BS_STRIDE)           // 2304
#define SMEM_BYTES ((AS_WORDS + BS_WORDS) * 4)   // 141312

// ---------------- scratch (static device allocations only) ----------------
static __device__ int    g_count[N_OUTN];
static __device__ int    g_offset[N_OUTN + 1];
static __device__ int    g_cursor[N_OUTN];
static __device__ int    g_bsum[NBLK_SCAN];
static __device__ int    g_in_sorted[NE];
static __device__ float4 g_ef_sorted[NE * 2];   // 8 floats / edge, sorted order

__device__ __forceinline__ int clampi(int v, int hi) {
    v = v < 0 ? 0 : v;
    return v >= hi ? hi - 1 : v;
}

__device__ __forceinline__ uint32_t f2tf32(float f) {
    uint32_t u;
    asm("cvt.rna.tf32.f32 %0, %1;" : "=r"(u) : "f"(f));
    return u;
}

// ---------------- k1: zero histogram ----------------
__global__ void k_zero() {
    int i = blockIdx.x * blockDim.x + threadIdx.x;
    if (i < N_OUTN) g_count[i] = 0;
}

// ---------------- k2: histogram of output node ids (indices INT32) ----------------
__global__ void k_hist(const int* __restrict__ idx) {
    int e = blockIdx.x * blockDim.x + threadIdx.x;
    if (e < NE) {
        int o = clampi(idx[2 * e], N_OUTN);
        atomicAdd(&g_count[o], 1);
    }
}

// ---------------- parallel coalesced exclusive scan (3 kernels) ----------------
__device__ __forceinline__ int block_scan_excl(int v, int* wsum, int* block_total) {
    int tid = threadIdx.x, lane = tid & 31, wid = tid >> 5;
    int x = v;
#pragma unroll
    for (int off = 1; off < 32; off <<= 1) {
        int y = __shfl_up_sync(0xffffffffu, x, off);
        if (lane >= off) x += y;
    }
    if (lane == 31) wsum[wid] = x;
    __syncthreads();
    if (tid == 0) {
        int run = 0;
#pragma unroll
        for (int j = 0; j < 8; j++) { int t = wsum[j]; wsum[j] = run; run += t; }
        *block_total = run;
    }
    __syncthreads();
    return x - v + wsum[wid];
}

__global__ void k_scan_a() {
    __shared__ int wsum[8];
    __shared__ int btot;
    int i = blockIdx.x * 256 + threadIdx.x;
    int v = (i < N_OUTN) ? g_count[i] : 0;
    int excl = block_scan_excl(v, wsum, &btot);
    if (i < N_OUTN) g_offset[i] = excl;
    if (threadIdx.x == 0) g_bsum[blockIdx.x] = btot;
}

__global__ void k_scan_b() {
    __shared__ int wsum[8];
    __shared__ int btot;
    int tid = threadIdx.x;
    int v = (tid < NBLK_SCAN) ? g_bsum[tid] : 0;
    int excl = block_scan_excl(v, wsum, &btot);
    if (tid < NBLK_SCAN) g_bsum[tid] = excl;
}

__global__ void k_scan_c() {
    int i = blockIdx.x * 256 + threadIdx.x;
    if (i < N_OUTN) {
        int v = g_offset[i] + g_bsum[blockIdx.x];
        g_offset[i] = v;
        g_cursor[i] = v;
    }
    if (i == 0) g_offset[N_OUTN] = NE;
}

// ---------------- k4: permute edges into segment-sorted order ----------------
__global__ void k_permute(const int* __restrict__ idx,
                          const float* __restrict__ ef) {
    int e = blockIdx.x * blockDim.x + threadIdx.x;
    if (e >= NE) return;
    int o  = clampi(idx[2 * e],     N_OUTN);
    int in = clampi(idx[2 * e + 1], N_INN);
    int pos = atomicAdd(&g_cursor[o], 1);
    pos = clampi(pos, NE);
    g_in_sorted[pos] = in;
    float4 v0, v1;
    v0.x = ef[0 * NE + e]; v0.y = ef[1 * NE + e];
    v0.z = ef[2 * NE + e]; v0.w = ef[3 * NE + e];
    v1.x = ef[4 * NE + e]; v1.y = ef[5 * NE + e];
    v1.z = ef[6 * NE + e]; v1.w = ef[7 * NE + e];
    g_ef_sorted[pos * 2]     = v0;
    g_ef_sorted[pos * 2 + 1] = v1;
}

// ---------------- fused aggregation + TF32 GEMM ----------------
__device__ __forceinline__ void fma16(float acc[16], float4 e0, float4 e1,
                                      float a0, float a1) {
    acc[0]  += e0.x * a0;  acc[1]  += e0.x * a1;
    acc[2]  += e0.y * a0;  acc[3]  += e0.y * a1;
    acc[4]  += e0.z * a0;  acc[5]  += e0.z * a1;
    acc[6]  += e0.w * a0;  acc[7]  += e0.w * a1;
    acc[8]  += e1.x * a0;  acc[9]  += e1.x * a1;
    acc[10] += e1.y * a0;  acc[11] += e1.y * a1;
    acc[12] += e1.z * a0;  acc[13] += e1.z * a1;
    acc[14] += e1.w * a0;  acc[15] += e1.w * a1;
}

extern __shared__ uint32_t s_dyn[];   // As[64][516] ++ Bs[32][72]

__global__ __launch_bounds__(512) void k_fused(const float* __restrict__ nf,
                                               const float* __restrict__ Kmat,
                                               const float* __restrict__ bias,
                                               float* __restrict__ out) {
    uint32_t* As = s_dyn;                 // [m][k] tf32 bits, stride 516
    uint32_t* Bs = s_dyn + AS_WORDS;      // [k][n] tf32 bits, stride 72

    int tid  = threadIdx.x;
    int warp = tid >> 5;                  // 0..15
    int lane = tid & 31;
    int m0   = blockIdx.x * BM;

    // ===== Phase 1: aggregate 4 nodes per warp into As =====
#pragma unroll 1
    for (int i = 0; i < 4; i++) {
        int m_local = warp * 4 + i;
        int node    = m0 + m_local;
        int start = 0, end = 0;
        if (node < N_OUTN) {
            start = g_offset[node];
            end   = g_offset[node + 1];
        }

        float acc[16];
#pragma unroll
        for (int j = 0; j < 16; j++) acc[j] = 0.f;

        int p = start;
        for (; p + 4 <= end; p += 4) {
            int in0 = g_in_sorted[p];
            int in1 = g_in_sorted[p + 1];
            int in2 = g_in_sorted[p + 2];
            int in3 = g_in_sorted[p + 3];
            float4 e00 = g_ef_sorted[p * 2 + 0], e01 = g_ef_sorted[p * 2 + 1];
            float4 e10 = g_ef_sorted[p * 2 + 2], e11 = g_ef_sorted[p * 2 + 3];
            float4 e20 = g_ef_sorted[p * 2 + 4], e21 = g_ef_sorted[p * 2 + 5];
            float4 e30 = g_ef_sorted[p * 2 + 6], e31 = g_ef_sorted[p * 2 + 7];
            float a00 = nf[in0 * NC + lane],      a01 = nf[in0 * NC + 32 + lane];
            float a10 = nf[in1 * NC + lane],      a11 = nf[in1 * NC + 32 + lane];
            float a20 = nf[in2 * NC + lane],      a21 = nf[in2 * NC + 32 + lane];
            float a30 = nf[in3 * NC + lane],      a31 = nf[in3 * NC + 32 + lane];
            fma16(acc, e00, e01, a00, a01);
            fma16(acc, e10, e11, a10, a11);
            fma16(acc, e20, e21, a20, a21);
            fma16(acc, e30, e31, a30, a31);
        }
        for (; p < end; p++) {
            int in0 = g_in_sorted[p];
            float4 e00 = g_ef_sorted[p * 2], e01 = g_ef_sorted[p * 2 + 1];
            float a00 = nf[in0 * NC + lane], a01 = nf[in0 * NC + 32 + lane];
            fma16(acc, e00, e01, a00, a01);
        }

        uint32_t* dst = As + m_local * AS_STRIDE;
#pragma unroll
        for (int t = 0; t < NT; t++) {
            dst[t * 64 + lane]      = f2tf32(acc[2 * t]);
            dst[t * 64 + 32 + lane] = f2tf32(acc[2 * t + 1]);
        }
    }
    __syncthreads();

    // ===== Phase 2: out_tile(64x64) = As(64x512) @ Kmat(512x64) + bias =====
    int gid = lane >> 2;       // 0..7
    int tig = lane & 3;        // 0..3
    int wm  = (warp & 3) * 16; // m sub-tile base
    int wn  = (warp >> 2) * 16;// n sub-tile base

    float facc[2][4];
#pragma unroll
    for (int nt = 0; nt < 2; nt++)
#pragma unroll
        for (int j = 0; j < 4; j++) facc[nt][j] = 0.f;

    for (int k0 = 0; k0 < KD; k0 += 32) {
        // Stage B tile 32x64: 512 float4 / 512 threads = 1 each
        {
            int kk = tid >> 4;        // 0..31
            int n4 = tid & 15;        // 0..15
            float4 v = *(const float4*)(Kmat + (size_t)(k0 + kk) * 64 + n4 * 4);
            uint32_t* brow = Bs + kk * BS_STRIDE + n4 * 4;
            brow[0] = f2tf32(v.x);
            brow[1] = f2tf32(v.y);
            brow[2] = f2tf32(v.z);
            brow[3] = f2tf32(v.w);
        }
        __syncthreads();

#pragma unroll
        for (int kk = 0; kk < 32; kk += 8) {
            // NOTE: As holds the FULL 512-wide K dimension -> index with k0 + kk
            const uint32_t* ar0 = As + (wm + gid) * AS_STRIDE + k0 + kk + tig;
            const uint32_t* ar1 = As + (wm + gid + 8) * AS_STRIDE + k0 + kk + tig;
            uint32_t a0 = ar0[0];
            uint32_t a1 = ar1[0];
            uint32_t a2 = ar0[4];
            uint32_t a3 = ar1[4];
#pragma unroll
            for (int nt = 0; nt < 2; nt++) {
                int n = wn + nt * 8 + gid;
                uint32_t b0 = Bs[(kk + tig) * BS_STRIDE + n];
                uint32_t b1 = Bs[(kk + tig + 4) * BS_STRIDE + n];
                asm volatile(
                    "mma.sync.aligned.m16n8k8.row.col.f32.tf32.tf32.f32 "
                    "{%0,%1,%2,%3}, {%4,%5,%6,%7}, {%8,%9}, {%0,%1,%2,%3};\n"
                    : "+f"(facc[nt][0]), "+f"(facc[nt][1]),
                      "+f"(facc[nt][2]), "+f"(facc[nt][3])
                    : "r"(a0), "r"(a1), "r"(a2), "r"(a3), "r"(b0), "r"(b1));
            }
        }
        __syncthreads();
    }

    // Epilogue
    int mA = m0 + wm + gid;
    int mB = mA + 8;
#pragma unroll
    for (int nt = 0; nt < 2; nt++) {
        int n = wn + nt * 8 + tig * 2;
        float b0 = bias[n], b1 = bias[n + 1];
        if (mA < N_OUTN) {
            float2 v; v.x = facc[nt][0] + b0; v.y = facc[nt][1] + b1;
            *(float2*)(out + (size_t)mA * NF + n) = v;
        }
        if (mB < N_OUTN) {
            float2 v; v.x = facc[nt][2] + b0; v.y = facc[nt][3] + b1;
            *(float2*)(out + (size_t)mB * NF + n) = v;
        }
    }
}

// ---------------- launch ----------------
extern "C" void kernel_launch(void* const* d_in, const int* in_sizes, int n_in,
                              void* d_out, int out_size) {
    const float* nf   = (const float*)d_in[0];   // node_features (50000,64)
    const float* ef   = (const float*)d_in[1];   // edge_features (8,800000)
    const int*   idx  = (const int*)d_in[2];     // indices (800000,2) int32
    const float* Kmat = (const float*)d_in[3];   // kernel (8,64,64)
    const float* bias = (const float*)d_in[4];   // bias (64,)
    float*       out  = (float*)d_out;           // (50000,64)

    // Unconditional (idempotent) — no static guards allowed by harness rules.
    cudaFuncSetAttribute(k_fused, cudaFuncAttributeMaxDynamicSharedMemorySize,
                         SMEM_BYTES);

    k_zero   <<<(N_OUTN + 255) / 256, 256>>>();
    k_hist   <<<(NE + 255) / 256, 256>>>(idx);
    k_scan_a <<<NBLK_SCAN, 256>>>();
    k_scan_b <<<1, 256>>>();
    k_scan_c <<<NBLK_SCAN, 256>>>();
    k_permute<<<(NE + 255) / 256, 256>>>(idx, ef);
    k_fused  <<<(N_OUTN + BM - 1) / BM, 512, SMEM_BYTES>>>(nf, Kmat, bias, out);
}

// round 8
// speedup vs baseline: 1.9554x; 1.9554x over previous
#include <cuda_runtime.h>
#include <cstdint>

// Problem constants
#define N_INN   50000
#define NC      64
#define NT      8
#define NE      800000
#define N_OUTN  50000
#define NF      64
#define KD      512   // NT*NC
#define NBLK_SCAN 196 // ceil(50000/256)

// ---------------- scratch (static device allocations only) ----------------
static __device__ int      g_count[N_OUTN];
static __device__ int      g_offset[N_OUTN + 1];
static __device__ int      g_cursor[N_OUTN];
static __device__ int      g_bsum[NBLK_SCAN];
static __device__ int      g_in_sorted[NE];
static __device__ float4   g_ef_sorted[NE * 2];                // 8 floats / edge, sorted
static __device__ uint32_t g_agg[(size_t)N_OUTN * KD];         // tf32 bits, 102.4 MB

__device__ __forceinline__ int clampi(int v, int hi) {
    v = v < 0 ? 0 : v;
    return v >= hi ? hi - 1 : v;
}

__device__ __forceinline__ uint32_t f2tf32(float f) {
    uint32_t u;
    asm("cvt.rna.tf32.f32 %0, %1;" : "=r"(u) : "f"(f));
    return u;
}

// ---------------- k1: zero histogram ----------------
__global__ void k_zero() {
    int i = blockIdx.x * blockDim.x + threadIdx.x;
    if (i < N_OUTN) g_count[i] = 0;
}

// ---------------- k2: histogram of output node ids (indices INT32) ----------------
__global__ void k_hist(const int* __restrict__ idx) {
    int e = blockIdx.x * blockDim.x + threadIdx.x;
    if (e < NE) {
        int o = clampi(idx[2 * e], N_OUTN);
        atomicAdd(&g_count[o], 1);
    }
}

// ---------------- parallel coalesced exclusive scan (3 kernels) ----------------
__device__ __forceinline__ int block_scan_excl(int v, int* wsum, int* block_total) {
    int tid = threadIdx.x, lane = tid & 31, wid = tid >> 5;
    int x = v;
#pragma unroll
    for (int off = 1; off < 32; off <<= 1) {
        int y = __shfl_up_sync(0xffffffffu, x, off);
        if (lane >= off) x += y;
    }
    if (lane == 31) wsum[wid] = x;
    __syncthreads();
    if (tid == 0) {
        int run = 0;
#pragma unroll
        for (int j = 0; j < 8; j++) { int t = wsum[j]; wsum[j] = run; run += t; }
        *block_total = run;
    }
    __syncthreads();
    return x - v + wsum[wid];
}

__global__ void k_scan_a() {
    __shared__ int wsum[8];
    __shared__ int btot;
    int i = blockIdx.x * 256 + threadIdx.x;
    int v = (i < N_OUTN) ? g_count[i] : 0;
    int excl = block_scan_excl(v, wsum, &btot);
    if (i < N_OUTN) g_offset[i] = excl;
    if (threadIdx.x == 0) g_bsum[blockIdx.x] = btot;
}

__global__ void k_scan_b() {
    __shared__ int wsum[8];
    __shared__ int btot;
    int tid = threadIdx.x;
    int v = (tid < NBLK_SCAN) ? g_bsum[tid] : 0;
    int excl = block_scan_excl(v, wsum, &btot);
    if (tid < NBLK_SCAN) g_bsum[tid] = excl;
}

__global__ void k_scan_c() {
    int i = blockIdx.x * 256 + threadIdx.x;
    if (i < N_OUTN) {
        int v = g_offset[i] + g_bsum[blockIdx.x];
        g_offset[i] = v;
        g_cursor[i] = v;
    }
    if (i == 0) g_offset[N_OUTN] = NE;
}

// ---------------- k4: permute edges into segment-sorted order ----------------
__global__ void k_permute(const int* __restrict__ idx,
                          const float* __restrict__ ef) {
    int e = blockIdx.x * blockDim.x + threadIdx.x;
    if (e >= NE) return;
    int o  = clampi(idx[2 * e],     N_OUTN);
    int in = clampi(idx[2 * e + 1], N_INN);
    int pos = atomicAdd(&g_cursor[o], 1);
    pos = clampi(pos, NE);
    g_in_sorted[pos] = in;
    float4 v0, v1;
    v0.x = ef[0 * NE + e]; v0.y = ef[1 * NE + e];
    v0.z = ef[2 * NE + e]; v0.w = ef[3 * NE + e];
    v1.x = ef[4 * NE + e]; v1.y = ef[5 * NE + e];
    v1.z = ef[6 * NE + e]; v1.w = ef[7 * NE + e];
    g_ef_sorted[pos * 2]     = v0;
    g_ef_sorted[pos * 2 + 1] = v1;
}

// ---------------- k5: per-output-node aggregation (one warp / node, unroll-4) ----------------
__device__ __forceinline__ void fma16(float acc[16], float4 e0, float4 e1,
                                      float a0, float a1) {
    acc[0]  += e0.x * a0;  acc[1]  += e0.x * a1;
    acc[2]  += e0.y * a0;  acc[3]  += e0.y * a1;
    acc[4]  += e0.z * a0;  acc[5]  += e0.z * a1;
    acc[6]  += e0.w * a0;  acc[7]  += e0.w * a1;
    acc[8]  += e1.x * a0;  acc[9]  += e1.x * a1;
    acc[10] += e1.y * a0;  acc[11] += e1.y * a1;
    acc[12] += e1.z * a0;  acc[13] += e1.z * a1;
    acc[14] += e1.w * a0;  acc[15] += e1.w * a1;
}

__global__ __launch_bounds__(256) void k_agg(const float* __restrict__ nf) {
    int gw   = (blockIdx.x * blockDim.x + threadIdx.x) >> 5;
    int lane = threadIdx.x & 31;
    if (gw >= N_OUTN) return;
    int start = g_offset[gw];
    int end   = g_offset[gw + 1];

    float acc[16];
#pragma unroll
    for (int i = 0; i < 16; i++) acc[i] = 0.f;

    int p = start;
    for (; p + 4 <= end; p += 4) {
        int in0 = g_in_sorted[p];
        int in1 = g_in_sorted[p + 1];
        int in2 = g_in_sorted[p + 2];
        int in3 = g_in_sorted[p + 3];
        float4 e00 = g_ef_sorted[p * 2 + 0], e01 = g_ef_sorted[p * 2 + 1];
        float4 e10 = g_ef_sorted[p * 2 + 2], e11 = g_ef_sorted[p * 2 + 3];
        float4 e20 = g_ef_sorted[p * 2 + 4], e21 = g_ef_sorted[p * 2 + 5];
        float4 e30 = g_ef_sorted[p * 2 + 6], e31 = g_ef_sorted[p * 2 + 7];
        float a00 = nf[in0 * NC + lane],      a01 = nf[in0 * NC + 32 + lane];
        float a10 = nf[in1 * NC + lane],      a11 = nf[in1 * NC + 32 + lane];
        float a20 = nf[in2 * NC + lane],      a21 = nf[in2 * NC + 32 + lane];
        float a30 = nf[in3 * NC + lane],      a31 = nf[in3 * NC + 32 + lane];
        fma16(acc, e00, e01, a00, a01);
        fma16(acc, e10, e11, a10, a11);
        fma16(acc, e20, e21, a20, a21);
        fma16(acc, e30, e31, a30, a31);
    }
    for (; p < end; p++) {
        int in0 = g_in_sorted[p];
        float4 e00 = g_ef_sorted[p * 2], e01 = g_ef_sorted[p * 2 + 1];
        float a00 = nf[in0 * NC + lane], a01 = nf[in0 * NC + 32 + lane];
        fma16(acc, e00, e01, a00, a01);
    }

    // Store tf32-rounded bits; GEMM A-staging becomes a pure copy.
    uint32_t* dst = g_agg + (size_t)gw * KD;
#pragma unroll
    for (int t = 0; t < NT; t++) {
        dst[t * 64 + lane]      = f2tf32(acc[2 * t]);
        dst[t * 64 + 32 + lane] = f2tf32(acc[2 * t + 1]);
    }
}

// ---------------- k6: TF32 tensor-core GEMM (validated R5 tiling) ----------------
// out(50000x64) = Agg(50000x512) @ Kmat(512x64) + bias
// 128 threads (4 warps). BM=64, BN=64, BK=32. mma.m16n8k8.tf32.
__global__ __launch_bounds__(128) void k_gemm_tf32(const float* __restrict__ Kmat,
                                                   const float* __restrict__ bias,
                                                   float* __restrict__ out) {
    __shared__ uint32_t As[64][36];   // [m][k], tf32 bits
    __shared__ uint32_t Bs[32][72];   // [k][n], tf32 bits

    int tid  = threadIdx.x;
    int warp = tid >> 5;
    int lane = tid & 31;
    int gid  = lane >> 2;     // 0..7
    int tig  = lane & 3;      // 0..3
    int m0   = blockIdx.x * 64;

    float acc[8][4];
#pragma unroll
    for (int nt = 0; nt < 8; nt++)
#pragma unroll
        for (int j = 0; j < 4; j++) acc[nt][j] = 0.f;

    for (int k0 = 0; k0 < KD; k0 += 32) {
        // Stage A tile 64x32: already tf32 bits, pure copy. 512 uint4 / 128 thr = 4 each
#pragma unroll
        for (int i = 0; i < 4; i++) {
            int fi  = tid + i * 128;
            int row = fi >> 3;          // 0..63
            int c4  = fi & 7;           // 0..7
            int gm  = m0 + row;
            uint4 v = (gm < N_OUTN)
                    ? *(const uint4*)(g_agg + (size_t)gm * KD + k0 + c4 * 4)
                    : make_uint4(0u, 0u, 0u, 0u);
            As[row][c4 * 4 + 0] = v.x;
            As[row][c4 * 4 + 1] = v.y;
            As[row][c4 * 4 + 2] = v.z;
            As[row][c4 * 4 + 3] = v.w;
        }
        // Stage B tile 32x64 with cvt
#pragma unroll
        for (int i = 0; i < 4; i++) {
            int fi = tid + i * 128;
            int kk = fi >> 4;           // 0..31
            int n4 = fi & 15;           // 0..15
            float4 v = *(const float4*)(Kmat + (size_t)(k0 + kk) * 64 + n4 * 4);
            Bs[kk][n4 * 4 + 0] = f2tf32(v.x);
            Bs[kk][n4 * 4 + 1] = f2tf32(v.y);
            Bs[kk][n4 * 4 + 2] = f2tf32(v.z);
            Bs[kk][n4 * 4 + 3] = f2tf32(v.w);
        }
        __syncthreads();

#pragma unroll
        for (int kk = 0; kk < 32; kk += 8) {
            int wm = warp * 16;
            uint32_t a0 = As[wm + gid][kk + tig];
            uint32_t a1 = As[wm + gid + 8][kk + tig];
            uint32_t a2 = As[wm + gid][kk + tig + 4];
            uint32_t a3 = As[wm + gid + 8][kk + tig + 4];
#pragma unroll
            for (int nt = 0; nt < 8; nt++) {
                uint32_t b0 = Bs[kk + tig][nt * 8 + gid];
                uint32_t b1 = Bs[kk + tig + 4][nt * 8 + gid];
                asm volatile(
                    "mma.sync.aligned.m16n8k8.row.col.f32.tf32.tf32.f32 "
                    "{%0,%1,%2,%3}, {%4,%5,%6,%7}, {%8,%9}, {%0,%1,%2,%3};\n"
                    : "+f"(acc[nt][0]), "+f"(acc[nt][1]),
                      "+f"(acc[nt][2]), "+f"(acc[nt][3])
                    : "r"(a0), "r"(a1), "r"(a2), "r"(a3), "r"(b0), "r"(b1));
            }
        }
        __syncthreads();
    }

    // Epilogue
    int mA = m0 + warp * 16 + gid;
    int mB = mA + 8;
#pragma unroll
    for (int nt = 0; nt < 8; nt++) {
        int n = nt * 8 + tig * 2;
        float b0 = bias[n], b1 = bias[n + 1];
        if (mA < N_OUTN) {
            float2 v; v.x = acc[nt][0] + b0; v.y = acc[nt][1] + b1;
            *(float2*)(out + (size_t)mA * NF + n) = v;
        }
        if (mB < N_OUTN) {
            float2 v; v.x = acc[nt][2] + b0; v.y = acc[nt][3] + b1;
            *(float2*)(out + (size_t)mB * NF + n) = v;
        }
    }
}

// ---------------- launch ----------------
extern "C" void kernel_launch(void* const* d_in, const int* in_sizes, int n_in,
                              void* d_out, int out_size) {
    const float* nf   = (const float*)d_in[0];   // node_features (50000,64)
    const float* ef   = (const float*)d_in[1];   // edge_features (8,800000)
    const int*   idx  = (const int*)d_in[2];     // indices (800000,2) int32
    const float* Kmat = (const float*)d_in[3];   // kernel (8,64,64)
    const float* bias = (const float*)d_in[4];   // bias (64,)
    float*       out  = (float*)d_out;           // (50000,64)

    k_zero   <<<(N_OUTN + 255) / 256, 256>>>();
    k_hist   <<<(NE + 255) / 256, 256>>>(idx);
    k_scan_a <<<NBLK_SCAN, 256>>>();
    k_scan_b <<<1, 256>>>();
    k_scan_c <<<NBLK_SCAN, 256>>>();
    k_permute<<<(NE + 255) / 256, 256>>>(idx, ef);
    k_agg    <<<(N_OUTN * 32 + 255) / 256, 256>>>(nf);
    k_gemm_tf32<<<(N_OUTN + 63) / 64, 128>>>(Kmat, bias, out);
}